// round 15
// baseline (speedup 1.0000x reference)
#include <cuda_runtime.h>
#include <cuda_fp16.h>
#include <math.h>
#include <stdint.h>

#define LAYERS 4
#define NH     128
#define FC     16
#define BB     16
#define TT     20
#define PRE    10
#define NPOS   256
#define NSTEP  19
#define OUT_FRAMES (BB*NSTEP*NPOS*FC)
#define HL     (BB*NPOS*NH)
#define XSZ    (BB*NPOS*FC)

#define NCH_L0   57
#define NCH_LN   100
#define BP_L0_U4 (4*NCH_L0*1024)
#define BP_LN_U4 (4*NCH_LN*1024)
#define BP_TOTAL (BP_L0_U4 + 3*BP_LN_U4)
#define TERMSZ   34560               // 240 rows * 144B max stride
#define SMEMSZ   TERMSZ

// ---------------- device scratch ----------------
__device__ __half  g_hhi[2][LAYERS][HL];      // parity buffers, layers 0-2 (+zero src)
__device__ __half  g_h3all[NSTEP][HL];        // per-t layer-3 history
__device__ float   g_c[2][LAYERS][HL];
__device__ __half  g_x0hi[NSTEP][XSZ];        // per-t layer-0 input
__device__ uint4   g_Bp[BP_TOTAL];
__device__ float   g_acc[2];

__device__ __forceinline__ float sigf(float x) {
    return __fdividef(1.f, 1.f + __expf(-x));
}
__device__ __forceinline__ float tanhf_(float x) {
    float e = __expf(-2.f * fabsf(x));
    float r = __fdividef(1.f - e, 1.f + e);
    return copysignf(r, x);
}
__device__ __forceinline__ uint32_t smem_to_u32(const void* p) {
    uint32_t a;
    asm("{ .reg .u64 t; cvta.to.shared.u64 t, %1; cvt.u32.u64 %0, t; }" : "=r"(a) : "l"(p));
    return a;
}
__device__ __forceinline__ void ldsm4(uint32_t (&r)[4], uint32_t a) {
    asm volatile("ldmatrix.sync.aligned.m8n8.x4.shared.b16 {%0,%1,%2,%3}, [%4];"
        : "=r"(r[0]), "=r"(r[1]), "=r"(r[2]), "=r"(r[3]) : "r"(a));
}
__device__ __forceinline__ void prefetchL1(const void* p) {
    asm volatile("prefetch.global.L1 [%0];" :: "l"(p));
}
__device__ __forceinline__ void mma_f32(float (&d)[4], const uint32_t (&a)[4],
                                        uint32_t b0, uint32_t b1) {
    asm volatile("mma.sync.aligned.m16n8k16.row.col.f32.f16.f16.f32 "
        "{%0,%1,%2,%3}, {%4,%5,%6,%7}, {%8,%9}, {%0,%1,%2,%3};"
        : "+f"(d[0]), "+f"(d[1]), "+f"(d[2]), "+f"(d[3])
        : "r"(a[0]), "r"(a[1]), "r"(a[2]), "r"(a[3]), "r"(b0), "r"(b1));
}

// ---------------- fused zero init ----------------
__global__ void zero_all(__half* h1, float* c, float* acc)
{
    int i = blockIdx.x * 256 + threadIdx.x;
    const int NH2 = LAYERS * HL / 2;
    if (i < NH2) ((float*)h1)[i] = 0.f;
    if (i < LAYERS * HL) c[i] = 0.f;
    if (i < 2) acc[i] = 0.f;
}

// ---------------- weight prepack (fp16 RN), all layers ----------------
__global__ void prepack_all(const float* __restrict__ Wx0, const float* __restrict__ Wh0,
                            const float* __restrict__ Wx1, const float* __restrict__ Wh1,
                            const float* __restrict__ Wx2, const float* __restrict__ Wh2,
                            const float* __restrict__ Wx3, const float* __restrict__ Wh3,
                            uint4* __restrict__ outb)
{
    int gidx = blockIdx.x * 256 + threadIdx.x;
    if (gidx >= BP_TOTAL) return;
    const float* Wx; const float* Wh; int NCH, isL0, idx;
    if (gidx < BP_L0_U4) { Wx = Wx0; Wh = Wh0; NCH = NCH_L0; isL0 = 1; idx = gidx; }
    else {
        int r = gidx - BP_L0_U4, l = r / BP_LN_U4;
        idx = r - l * BP_LN_U4; NCH = NCH_LN; isL0 = 0;
        Wx = (l == 0) ? Wx1 : (l == 1) ? Wx2 : Wx3;
        Wh = (l == 0) ? Wh1 : (l == 1) ? Wh2 : Wh3;
    }
    int lane = idx & 31;
    int kp   = (idx >> 5) & 1;
    int n8t  = (idx >> 6) & 15;
    int rest = idx >> 10;
    int kc   = rest % NCH;
    int ntile = rest / NCH;
    int nglob = ntile * 128 + n8t * 8 + (lane >> 2);
    int hc = nglob >> 2, g = nglob & 3;

    uint32_t q[4];
#pragma unroll
    for (int j = 0; j < 4; j++) {
        uint32_t rr = 0;
#pragma unroll
        for (int h = 0; h < 2; h++) {
            int klocal = (kp * 2 + (j >> 1)) * 16 + (j & 1) * 8 + (lane & 3) * 2 + h;
            float w;
            if (isL0) {
                if (kc < 7) {
                    int ks = klocal >> 4, kk = klocal & 15;
                    int tap = kc * 4 + ks;
                    w = (tap <= 24) ? Wx[((g * 128 + hc) * 16 + kk) * 25 + tap] : 0.f;
                } else {
                    int j2 = kc - 7, seg = j2 / 25, tap = j2 % 25;
                    int c = seg * 64 + klocal;
                    w = Wh[((g * 128 + hc) * 128 + c) * 25 + tap];
                }
            } else {
                int seg = kc / 25, tap = kc % 25;
                int c = (seg & 1) * 64 + klocal;
                const float* src = (seg < 2) ? Wx : Wh;
                w = src[((g * 128 + hc) * 128 + c) * 25 + tap];
            }
            rr |= (uint32_t)__half_as_ushort(__float2half(w)) << (16 * h);
        }
        q[j] = rr;
    }
    outb[gidx] = make_uint4(q[0], q[1], q[2], q[3]);
}

// ---------------- fused mma.sync GEMM + LSTM pointwise ----------------
template<bool L0>
__global__ void __launch_bounds__(256, 2) gemm_lstm(
    const __half* __restrict__ xhi,
    const __half* __restrict__ hhi,
    const uint4* __restrict__ Bp,
    const float* __restrict__ cprev, float* __restrict__ cnew,
    __half* __restrict__ hhiout)
{
    constexpr int NCH = L0 ? NCH_L0 : NCH_LN;
    extern __shared__ __align__(128) char smem[];
    const int tid = threadIdx.x, lane = tid & 31, wid = tid >> 5;
    const int wm = wid & 3, wn = wid >> 2;
    const int nt64 = blockIdx.x, mt2 = blockIdx.y;
    const int ntile128 = nt64 >> 1, n8base = (nt64 & 1) * 8;
    const int b = mt2 >> 1, pos0 = (mt2 & 1) << 7, yb0 = (mt2 & 1) << 3;
    const uint32_t sA = smem_to_u32(smem);
    const int half16 = (lane >> 4) * 16;

    uint32_t abase144[2], abase48[2];
#pragma unroll
    for (int mt = 0; mt < 2; mt++) {
        int pos = pos0 + wm * 32 + mt * 16 + (lane & 15);
        int rowb = ((pos >> 4) - yb0) * 20 + (pos & 15);
        abase144[mt] = sA + (uint32_t)rowb * 144 + half16;
        abase48[mt]  = sA + (uint32_t)rowb * 48  + half16;
    }

    float acc[2][4][4];
#pragma unroll
    for (int a = 0; a < 2; a++)
#pragma unroll
        for (int c = 0; c < 4; c++)
#pragma unroll
            for (int d = 0; d < 4; d++) acc[a][c][d] = 0.f;

    auto stage = [&](const __half* src, int CIN, int coff, int nu4, int stride) {
        __syncthreads();
        for (int r = tid; r < 240; r += 256) {
            int yy = yb0 - 2 + r / 20, xx = r % 20 - 2;
            uint4* dst = (uint4*)(smem + r * stride);
            if (yy >= 0 && yy < 16 && xx >= 0 && xx < 16) {
                const uint4* sp = (const uint4*)(src +
                    (size_t)(((b << 8) + (yy << 4) + xx)) * CIN + coff);
                for (int j = 0; j < nu4; j++) dst[j] = sp[j];
            } else {
                uint4 z = make_uint4(0, 0, 0, 0);
                for (int j = 0; j < nu4; j++) dst[j] = z;
            }
        }
        __syncthreads();
    };

    const int fragoff = (n8base + wn * 4) * 64 + lane;
    const int pfoff = 1024 + n8base * 64 + tid * 8;   // next-kc CTA half, 64 lines

    for (int kc = 0; kc < NCH; kc++) {
        const uint4* bc = Bp + ((size_t)(ntile128 * NCH + kc) * 1024);

        // B fragments + precise half-tile prefetch, issued BEFORE staging sync
        uint4 Breg[4][2];
#pragma unroll
        for (int nt = 0; nt < 4; nt++)
#pragma unroll
            for (int kp = 0; kp < 2; kp++)
                Breg[nt][kp] = bc[fragoff + nt * 64 + kp * 32];
        if (kc + 1 < NCH && tid < 64)
            prefetchL1(bc + pfoff);

        int tap = 0;
        bool xseg = false;
        if (L0) {
            if (kc < 7) {
                xseg = true;
                if (kc == 0) stage(xhi, 16, 0, 2, 48);
            } else {
                int j = kc - 7, seg = j / 25; tap = j % 25;
                if (tap == 0) stage(hhi, 128, seg * 64, 8, 144);
            }
        } else {
            int seg = kc / 25; tap = kc % 25;
            if (tap == 0)
                stage((seg < 2) ? xhi : hhi, 128, (seg & 1) * 64, 8, 144);
        }

        int tap5y = tap / 5, tap5x = tap - tap5y * 5;
        uint32_t tapoff144 = (uint32_t)(tap5y * 20 + tap5x) * 144;

#pragma unroll
        for (int ks = 0; ks < 4; ks++) {
            uint32_t Ah[2][4];
            if (L0 && xseg) {
                int tapk = kc * 4 + ks; if (tapk > 24) tapk = 24;
                int ky = tapk / 5, kx = tapk - ky * 5;
                uint32_t off = (uint32_t)(ky * 20 + kx) * 48;
#pragma unroll
                for (int mt = 0; mt < 2; mt++)
                    ldsm4(Ah[mt], abase48[mt] + off);
            } else {
                uint32_t off = tapoff144 + (uint32_t)(ks * 32);
#pragma unroll
                for (int mt = 0; mt < 2; mt++)
                    ldsm4(Ah[mt], abase144[mt] + off);
            }
#pragma unroll
            for (int mt = 0; mt < 2; mt++) {
#pragma unroll
                for (int nt = 0; nt < 4; nt++) {
                    uint4 bh4 = Breg[nt][ks >> 1];
                    uint32_t bh0 = (ks & 1) ? bh4.z : bh4.x;
                    uint32_t bh1 = (ks & 1) ? bh4.w : bh4.y;
                    mma_f32(acc[mt][nt], Ah[mt], bh0, bh1);
                }
            }
        }
    }

    // ---- LSTM pointwise epilogue (fast math) ----
    const int role = lane & 1;
#pragma unroll
    for (int mt = 0; mt < 2; mt++) {
#pragma unroll
        for (int nt = 0; nt < 4; nt++) {
            float* a = acc[mt][nt];
            float s0 = role ? a[0] : a[2];
            float s1 = role ? a[1] : a[3];
            float r0 = __shfl_xor_sync(0xffffffffu, s0, 1);
            float r1 = __shfl_xor_sync(0xffffffffu, s1, 1);
            float gi, gf, gg, go;
            int mrow;
            if (role == 0) { gi = a[0]; gf = a[1]; gg = r0; go = r1; mrow = lane >> 2; }
            else           { gi = r0;  gf = r1;  gg = a[2]; go = a[3]; mrow = (lane >> 2) + 8; }
            int pos = pos0 + wm * 32 + mt * 16 + mrow;
            int hc = nt64 * 16 + wn * 8 + nt * 2 + ((lane & 3) >> 1);
            size_t ci = ((size_t)((b << 8) + pos) << 7) + hc;
            float cv = sigf(gf + 1.0f) * cprev[ci] + sigf(gi) * tanhf_(gg);
            cnew[ci] = cv;
            hhiout[ci] = __float2half(sigf(go) * tanhf_(cv));
        }
    }
}

// ---------------- 1x1 projection (on-chain, t>=9): out + masked x0[t+1] --------
__global__ void xgen_k(const __half* __restrict__ h3,
                       const float* __restrict__ Wlast,
                       const float* __restrict__ frames, const float* __restrict__ maskT,
                       __half* __restrict__ x0next,
                       float* __restrict__ out, int t)
{
    __shared__ float s_w[FC * NH];
    int b = blockIdx.x, tid = threadIdx.x;
    for (int i = tid; i < FC * NH; i += 256) s_w[i] = Wlast[i];
    __syncthreads();
    int pos = blockIdx.y * 128 + (tid >> 1);
    int half = tid & 1;
    size_t hb = (((size_t)(b * 256 + pos)) << 7) + half * 64;
    float acc[FC];
#pragma unroll
    for (int f = 0; f < FC; f++) acc[f] = 0.f;
    for (int ch = 0; ch < 64; ch++) {
        float hv = __half2float(h3[hb + ch]);
#pragma unroll
        for (int f = 0; f < FC; f++) acc[f] += hv * s_w[f * NH + half * 64 + ch];
    }
#pragma unroll
    for (int f = 0; f < FC; f++)
        acc[f] += __shfl_xor_sync(0xffffffffu, acc[f], 1);

    if (half == 0) {
        size_t ob = ((size_t)(b * NSTEP + t) * 256 + pos) * 16;
#pragma unroll
        for (int f = 0; f < FC; f++) out[ob + f] = acc[f];

        int tn = t + 1;
        if (tn < NSTEP) {
            size_t fb = ((size_t)(b * TT + tn) * 256 + pos) * 16;
            size_t xb = ((size_t)(b * 256 + pos)) * 16;
#pragma unroll
            for (int f = 0; f < FC; f++) {
                float fr = frames[fb + f];
                float mm = maskT[((size_t)(b * (NSTEP - PRE) + (tn - PRE)) * 256 + pos) * 16 + f];
                x0next[xb + f] = __float2half(mm * fr + (1.f - mm) * acc[f]);
            }
        }
    }
}

// ---------------- batched off-chain xgen: t in {0..8, 18}, out[] only ----------
__global__ void xgen_batch(const __half* __restrict__ h3all,
                           const float* __restrict__ Wlast,
                           float* __restrict__ out)
{
    __shared__ float s_w[FC * NH];
    int b = blockIdx.x, tid = threadIdx.x;
    int t = (blockIdx.z < 9) ? (int)blockIdx.z : 18;
    const __half* h3 = h3all + (size_t)t * HL;
    for (int i = tid; i < FC * NH; i += 256) s_w[i] = Wlast[i];
    __syncthreads();
    int pos = blockIdx.y * 128 + (tid >> 1);
    int half = tid & 1;
    size_t hb = (((size_t)(b * 256 + pos)) << 7) + half * 64;
    float acc[FC];
#pragma unroll
    for (int f = 0; f < FC; f++) acc[f] = 0.f;
    for (int ch = 0; ch < 64; ch++) {
        float hv = __half2float(h3[hb + ch]);
#pragma unroll
        for (int f = 0; f < FC; f++) acc[f] += hv * s_w[f * NH + half * 64 + ch];
    }
#pragma unroll
    for (int f = 0; f < FC; f++)
        acc[f] += __shfl_xor_sync(0xffffffffu, acc[f], 1);
    if (half == 0) {
        size_t ob = ((size_t)(b * NSTEP + t) * 256 + pos) * 16;
#pragma unroll
        for (int f = 0; f < FC; f++) out[ob + f] = acc[f];
    }
}

// ---------------- precompute x0 for t = 0..PRE-1 (ground truth) ----------------
__global__ void maskpre_k(const float* __restrict__ frames, __half* __restrict__ x0all)
{
    int idx = blockIdx.x * 256 + threadIdx.x;
    int t = blockIdx.y;
    if (idx >= XSZ) return;
    int c = idx & 15, pos = (idx >> 4) & 255, b = idx >> 12;
    x0all[(size_t)t * XSZ + idx] =
        __float2half(frames[(((size_t)(b * TT + t)) * 256 + pos) * 16 + c]);
}

// ---------------- losses ----------------
__global__ void mse_k(const float* __restrict__ pred, const float* __restrict__ frames,
                      float* __restrict__ acc)
{
    __shared__ float s_red[256];
    float sum = 0.f;
    for (int idx = blockIdx.x * 256 + threadIdx.x; idx < OUT_FRAMES; idx += gridDim.x * 256) {
        int c = idx & 15, pos = (idx >> 4) & 255, r = idx >> 12;
        int t = r % NSTEP, b = r / NSTEP;
        float d = pred[idx] - frames[(((size_t)(b * TT + t + 1)) * 256 + pos) * 16 + c];
        sum += d * d;
    }
    s_red[threadIdx.x] = sum;
    __syncthreads();
    for (int s = 128; s > 0; s >>= 1) {
        if (threadIdx.x < s) s_red[threadIdx.x] += s_red[threadIdx.x + s];
        __syncthreads();
    }
    if (threadIdx.x == 0) atomicAdd(&acc[0], s_red[0]);
}

__global__ void heur_k(const float* __restrict__ pred, const float* __restrict__ frames,
                       float* __restrict__ acc)
{
    int idx = threadIdx.x;
    if (idx >= NSTEP * 16) return;
    int t = idx / 16, w = idx % 16;
    float xp = 0.f, xt = 0.f;
    for (int c = 0; c < FC; c++) {
        float vals[BB]; float mx = -1e30f;
        for (int b = 0; b < BB; b++) {
            vals[b] = pred[(((size_t)(b * NSTEP + t)) * 256 + w) * 16 + c];
            mx = fmaxf(mx, vals[b]);
        }
        float s = 0.f, sw = 0.f;
        for (int b = 0; b < BB; b++) { float e = expf(vals[b] - mx); s += e; sw += e * (float)b; }
        xp += sw / s;
        mx = -1e30f;
        for (int b = 0; b < BB; b++) {
            vals[b] = frames[(((size_t)(b * TT + t + 1)) * 256 + w) * 16 + c];
            mx = fmaxf(mx, vals[b]);
        }
        s = 0.f; sw = 0.f;
        for (int b = 0; b < BB; b++) { float e = expf(vals[b] - mx); s += e; sw += e * (float)b; }
        xt += sw / s;
    }
    xp *= (1.f / FC); xt *= (1.f / FC);
    float d = xp - xt;
    atomicAdd(&acc[1], d * d);
}

__global__ void finalize_k(const float* __restrict__ acc, float* __restrict__ out_loss)
{
    out_loss[0] = acc[0] / (float)OUT_FRAMES + acc[1] / (float)(NSTEP * 16);
}

// ---------------- host orchestration ----------------
extern "C" void kernel_launch(void* const* d_in, const int* in_sizes, int n_in,
                              void* d_out, int out_size)
{
    const float* frames = (const float*)d_in[0];
    const float* maskp  = (const float*)d_in[1];
    const float* Wlast  = (const float*)d_in[10];
    float* out = (float*)d_out;

    void* p;
    cudaGetSymbolAddress(&p, g_hhi);   __half* hhi   = (__half*)p;
    cudaGetSymbolAddress(&p, g_h3all); __half* h3all = (__half*)p;
    cudaGetSymbolAddress(&p, g_c);     float* cbuf   = (float*)p;
    cudaGetSymbolAddress(&p, g_x0hi);  __half* x0all = (__half*)p;
    cudaGetSymbolAddress(&p, g_Bp);    uint4* bp     = (uint4*)p;
    cudaGetSymbolAddress(&p, g_acc);   float* accb   = (float*)p;

    cudaFuncSetAttribute(gemm_lstm<true>,  cudaFuncAttributeMaxDynamicSharedMemorySize, SMEMSZ);
    cudaFuncSetAttribute(gemm_lstm<false>, cudaFuncAttributeMaxDynamicSharedMemorySize, SMEMSZ);

    zero_all<<<(LAYERS * HL + 255) / 256, 256>>>(hhi, cbuf, accb);
    prepack_all<<<(BP_TOTAL + 255) / 256, 256>>>(
        (const float*)d_in[2], (const float*)d_in[3],
        (const float*)d_in[4], (const float*)d_in[5],
        (const float*)d_in[6], (const float*)d_in[7],
        (const float*)d_in[8], (const float*)d_in[9], bp);
    {
        dim3 mg((XSZ + 255) / 256, PRE);
        maskpre_k<<<mg, 256>>>(frames, x0all);
    }

    // layer-3 zero history source for t=0: hhi parity-0 layer-3 slot (zeroed, never written)
    __half* h3zero = hhi + (size_t)3 * HL;

    dim3 ggrid(8, 32);
    dim3 xgrid(BB, 2);
    for (int t = 0; t < NSTEP; t++) {
        int r = t & 1, w = 1 - r;
        __half* hhr = hhi + (size_t)r * LAYERS * HL;
        __half* hhw = hhi + (size_t)w * LAYERS * HL;
        float* cr = cbuf + (size_t)r * LAYERS * HL;
        float* cw = cbuf + (size_t)w * LAYERS * HL;

        gemm_lstm<true><<<ggrid, 256, SMEMSZ>>>(
            x0all + (size_t)t * XSZ, hhr, bp, cr, cw, hhw);
        for (int l = 1; l < 3; l++) {
            gemm_lstm<false><<<ggrid, 256, SMEMSZ>>>(
                hhw + (size_t)(l - 1) * HL,
                hhr + (size_t)l * HL,
                bp + BP_L0_U4 + (size_t)(l - 1) * BP_LN_U4,
                cr + (size_t)l * HL, cw + (size_t)l * HL,
                hhw + (size_t)l * HL);
        }
        // layer 3: recurrent from h3 history, write to per-t slot
        gemm_lstm<false><<<ggrid, 256, SMEMSZ>>>(
            hhw + (size_t)2 * HL,
            (t == 0) ? h3zero : (h3all + (size_t)(t - 1) * HL),
            bp + BP_L0_U4 + (size_t)2 * BP_LN_U4,
            cr + (size_t)3 * HL, cw + (size_t)3 * HL,
            h3all + (size_t)t * HL);

        // on-chain xgen only when x(t+1) depends on it (t+1 >= PRE)
        if (t >= PRE - 1 && t < NSTEP - 1) {
            xgen_k<<<xgrid, 256>>>(h3all + (size_t)t * HL, Wlast,
                                   frames, maskp,
                                   x0all + (size_t)(t + 1) * XSZ, out, t);
        }
    }

    // batched off-chain xgen for t in {0..8, 18}
    {
        dim3 bg(BB, 2, 10);
        xgen_batch<<<bg, 256>>>(h3all, Wlast, out);
    }

    mse_k<<<1024, 256>>>(out, frames, accb);
    heur_k<<<1, NSTEP * 16>>>(out, frames, accb);
    finalize_k<<<1, 1>>>(accb, out + (out_size - 1));
}

// round 16
// speedup vs baseline: 1.0200x; 1.0200x over previous
#include <cuda_runtime.h>
#include <cuda_fp16.h>
#include <math.h>
#include <stdint.h>

#define LAYERS 4
#define NH     128
#define FC     16
#define BB     16
#define TT     20
#define PRE    10
#define NPOS   256
#define NSTEP  19
#define OUT_FRAMES (BB*NSTEP*NPOS*FC)
#define HL     (BB*NPOS*NH)

#define NCH_L0   57
#define NCH_LN   100
#define BP_L0_U4 (4*NCH_L0*1024)
#define BP_LN_U4 (4*NCH_LN*1024)
#define BP_TOTAL (BP_L0_U4 + 3*BP_LN_U4)
#define TERMSZ   34560               // 240 rows * 144B max stride
#define SMEMSZ   TERMSZ

// ---------------- device scratch ----------------
__device__ __half  g_hhi[2][LAYERS][HL];
__device__ float   g_c[2][LAYERS][HL];
__device__ __half  g_x0hi[BB*NPOS*FC];
__device__ uint4   g_Bp[BP_TOTAL];
__device__ float   g_acc[2];

// fast sigmoid / tanh: single MUFU exp + approx reciprocal (err ~1e-6)
__device__ __forceinline__ float sigf(float x) {
    return __fdividef(1.f, 1.f + __expf(-x));
}
__device__ __forceinline__ float tanhf_(float x) {
    float e = __expf(-2.f * fabsf(x));
    float r = __fdividef(1.f - e, 1.f + e);
    return copysignf(r, x);
}
__device__ __forceinline__ uint32_t smem_to_u32(const void* p) {
    uint32_t a;
    asm("{ .reg .u64 t; cvta.to.shared.u64 t, %1; cvt.u32.u64 %0, t; }" : "=r"(a) : "l"(p));
    return a;
}
__device__ __forceinline__ void ldsm4(uint32_t (&r)[4], uint32_t a) {
    asm volatile("ldmatrix.sync.aligned.m8n8.x4.shared.b16 {%0,%1,%2,%3}, [%4];"
        : "=r"(r[0]), "=r"(r[1]), "=r"(r[2]), "=r"(r[3]) : "r"(a));
}
__device__ __forceinline__ void prefetchL1(const void* p) {
    asm volatile("prefetch.global.L1 [%0];" :: "l"(p));
}
__device__ __forceinline__ void mma_f32(float (&d)[4], const uint32_t (&a)[4],
                                        uint32_t b0, uint32_t b1) {
    asm volatile("mma.sync.aligned.m16n8k16.row.col.f32.f16.f16.f32 "
        "{%0,%1,%2,%3}, {%4,%5,%6,%7}, {%8,%9}, {%0,%1,%2,%3};"
        : "+f"(d[0]), "+f"(d[1]), "+f"(d[2]), "+f"(d[3])
        : "r"(a[0]), "r"(a[1]), "r"(a[2]), "r"(a[3]), "r"(b0), "r"(b1));
}

// ---------------- fused zero init ----------------
__global__ void zero_all(__half* h1, float* c, float* acc)
{
    int i = blockIdx.x * 256 + threadIdx.x;
    const int NH2 = LAYERS * HL / 2;
    if (i < NH2) ((float*)h1)[i] = 0.f;
    if (i < LAYERS * HL) c[i] = 0.f;
    if (i < 2) acc[i] = 0.f;
}

// ---------------- weight prepack (fp16 RN), all layers ----------------
__global__ void prepack_all(const float* __restrict__ Wx0, const float* __restrict__ Wh0,
                            const float* __restrict__ Wx1, const float* __restrict__ Wh1,
                            const float* __restrict__ Wx2, const float* __restrict__ Wh2,
                            const float* __restrict__ Wx3, const float* __restrict__ Wh3,
                            uint4* __restrict__ outb)
{
    int gidx = blockIdx.x * 256 + threadIdx.x;
    if (gidx >= BP_TOTAL) return;
    const float* Wx; const float* Wh; int NCH, isL0, idx;
    if (gidx < BP_L0_U4) { Wx = Wx0; Wh = Wh0; NCH = NCH_L0; isL0 = 1; idx = gidx; }
    else {
        int r = gidx - BP_L0_U4, l = r / BP_LN_U4;
        idx = r - l * BP_LN_U4; NCH = NCH_LN; isL0 = 0;
        Wx = (l == 0) ? Wx1 : (l == 1) ? Wx2 : Wx3;
        Wh = (l == 0) ? Wh1 : (l == 1) ? Wh2 : Wh3;
    }
    int lane = idx & 31;
    int kp   = (idx >> 5) & 1;
    int n8t  = (idx >> 6) & 15;
    int rest = idx >> 10;
    int kc   = rest % NCH;
    int ntile = rest / NCH;
    int nglob = ntile * 128 + n8t * 8 + (lane >> 2);
    int hc = nglob >> 2, g = nglob & 3;

    uint32_t q[4];
#pragma unroll
    for (int j = 0; j < 4; j++) {
        uint32_t rr = 0;
#pragma unroll
        for (int h = 0; h < 2; h++) {
            int klocal = (kp * 2 + (j >> 1)) * 16 + (j & 1) * 8 + (lane & 3) * 2 + h;
            float w;
            if (isL0) {
                if (kc < 7) {
                    int ks = klocal >> 4, kk = klocal & 15;
                    int tap = kc * 4 + ks;
                    w = (tap <= 24) ? Wx[((g * 128 + hc) * 16 + kk) * 25 + tap] : 0.f;
                } else {
                    int j2 = kc - 7, seg = j2 / 25, tap = j2 % 25;
                    int c = seg * 64 + klocal;
                    w = Wh[((g * 128 + hc) * 128 + c) * 25 + tap];
                }
            } else {
                int seg = kc / 25, tap = kc % 25;
                int c = (seg & 1) * 64 + klocal;
                const float* src = (seg < 2) ? Wx : Wh;
                w = src[((g * 128 + hc) * 128 + c) * 25 + tap];
            }
            rr |= (uint32_t)__half_as_ushort(__float2half(w)) << (16 * h);
        }
        q[j] = rr;
    }
    outb[gidx] = make_uint4(q[0], q[1], q[2], q[3]);
}

// ---------------- fused mma.sync GEMM + LSTM pointwise ----------------
// grid (8 n-tiles of 64, 32 m-tiles of 128); 256 thr = 8 warps (4 wm x 2 wn),
// warp tile 32m x 32n, 2 CTAs/SM. Pure fp16 weights. Hoisted A addressing,
// PRECISE cooperative L1 prefetch (CTA's 8KB half of B(kc+1)), fast-math epilogue.
template<bool L0>
__global__ void __launch_bounds__(256, 2) gemm_lstm(
    const __half* __restrict__ xhi,
    const __half* __restrict__ hhi,
    const uint4* __restrict__ Bp,
    const float* __restrict__ cprev, float* __restrict__ cnew,
    __half* __restrict__ hhiout)
{
    constexpr int NCH = L0 ? NCH_L0 : NCH_LN;
    extern __shared__ __align__(128) char smem[];
    const int tid = threadIdx.x, lane = tid & 31, wid = tid >> 5;
    const int wm = wid & 3, wn = wid >> 2;
    const int nt64 = blockIdx.x, mt2 = blockIdx.y;
    const int ntile128 = nt64 >> 1, n8base = (nt64 & 1) * 8;
    const int b = mt2 >> 1, pos0 = (mt2 & 1) << 7, yb0 = (mt2 & 1) << 3;
    const uint32_t sA = smem_to_u32(smem);
    const int half16 = (lane >> 4) * 16;

    // per-lane hoisted A base addresses (row = ylocal*20 + xcol)
    uint32_t abase144[2], abase48[2];
#pragma unroll
    for (int mt = 0; mt < 2; mt++) {
        int pos = pos0 + wm * 32 + mt * 16 + (lane & 15);
        int rowb = ((pos >> 4) - yb0) * 20 + (pos & 15);
        abase144[mt] = sA + (uint32_t)rowb * 144 + half16;
        abase48[mt]  = sA + (uint32_t)rowb * 48  + half16;
    }

    float acc[2][4][4];
#pragma unroll
    for (int a = 0; a < 2; a++)
#pragma unroll
        for (int c = 0; c < 4; c++)
#pragma unroll
            for (int d = 0; d < 4; d++) acc[a][c][d] = 0.f;

    // stage padded raw hi image: 240 rows (12 y x 20 x)
    auto stage = [&](const __half* src, int CIN, int coff, int nu4, int stride) {
        __syncthreads();
        for (int r = tid; r < 240; r += 256) {
            int yy = yb0 - 2 + r / 20, xx = r % 20 - 2;
            uint4* dst = (uint4*)(smem + r * stride);
            if (yy >= 0 && yy < 16 && xx >= 0 && xx < 16) {
                const uint4* sp = (const uint4*)(src +
                    (size_t)(((b << 8) + (yy << 4) + xx)) * CIN + coff);
                for (int j = 0; j < nu4; j++) dst[j] = sp[j];
            } else {
                uint4 z = make_uint4(0, 0, 0, 0);
                for (int j = 0; j < nu4; j++) dst[j] = z;
            }
        }
        __syncthreads();
    };

    const int fragoff = (n8base + wn * 4) * 64 + lane;

    for (int kc = 0; kc < NCH; kc++) {
        int tap = 0;
        bool xseg = false;
        if (L0) {
            if (kc < 7) {
                xseg = true;
                if (kc == 0) stage(xhi, 16, 0, 2, 48);
            } else {
                int j = kc - 7, seg = j / 25; tap = j % 25;
                if (tap == 0) stage(hhi, 128, seg * 64, 8, 144);
            }
        } else {
            int seg = kc / 25; tap = kc % 25;
            if (tap == 0)
                stage((seg < 2) ? xhi : hhi, 128, (seg & 1) * 64, 8, 144);
        }

        // B fragments for this kc (L1-resident thanks to prefetch)
        const uint4* bc = Bp + ((size_t)(ntile128 * NCH + kc) * 1024);
        uint4 Breg[4][2];
#pragma unroll
        for (int nt = 0; nt < 4; nt++)
#pragma unroll
            for (int kp = 0; kp < 2; kp++)
                Breg[nt][kp] = bc[fragoff + nt * 64 + kp * 32];

        // precise prefetch: only this CTA's 8KB half of next kc's B (64 lines)
        if (kc + 1 < NCH && tid < 64)
            prefetchL1(bc + 1024 + n8base * 64 + tid * 8);

        // uniform per-kc tap offset (scalar)
        int tap5y = tap / 5, tap5x = tap - tap5y * 5;
        uint32_t tapoff144 = (uint32_t)(tap5y * 20 + tap5x) * 144;

#pragma unroll
        for (int ks = 0; ks < 4; ks++) {
            uint32_t Ah[2][4];
            if (L0 && xseg) {
                int tapk = kc * 4 + ks; if (tapk > 24) tapk = 24;
                int ky = tapk / 5, kx = tapk - ky * 5;
                uint32_t off = (uint32_t)(ky * 20 + kx) * 48;
#pragma unroll
                for (int mt = 0; mt < 2; mt++)
                    ldsm4(Ah[mt], abase48[mt] + off);
            } else {
                uint32_t off = tapoff144 + (uint32_t)(ks * 32);
#pragma unroll
                for (int mt = 0; mt < 2; mt++)
                    ldsm4(Ah[mt], abase144[mt] + off);
            }
#pragma unroll
            for (int mt = 0; mt < 2; mt++) {
#pragma unroll
                for (int nt = 0; nt < 4; nt++) {
                    uint4 bh4 = Breg[nt][ks >> 1];
                    uint32_t bh0 = (ks & 1) ? bh4.z : bh4.x;
                    uint32_t bh1 = (ks & 1) ? bh4.w : bh4.y;
                    mma_f32(acc[mt][nt], Ah[mt], bh0, bh1);
                }
            }
        }
    }

    // ---- LSTM pointwise epilogue (fast math) ----
    const int role = lane & 1;
#pragma unroll
    for (int mt = 0; mt < 2; mt++) {
#pragma unroll
        for (int nt = 0; nt < 4; nt++) {
            float* a = acc[mt][nt];
            float s0 = role ? a[0] : a[2];
            float s1 = role ? a[1] : a[3];
            float r0 = __shfl_xor_sync(0xffffffffu, s0, 1);
            float r1 = __shfl_xor_sync(0xffffffffu, s1, 1);
            float gi, gf, gg, go;
            int mrow;
            if (role == 0) { gi = a[0]; gf = a[1]; gg = r0; go = r1; mrow = lane >> 2; }
            else           { gi = r0;  gf = r1;  gg = a[2]; go = a[3]; mrow = (lane >> 2) + 8; }
            int pos = pos0 + wm * 32 + mt * 16 + mrow;
            int hc = nt64 * 16 + wn * 8 + nt * 2 + ((lane & 3) >> 1);
            size_t ci = ((size_t)((b << 8) + pos) << 7) + hc;
            float cv = sigf(gf + 1.0f) * cprev[ci] + sigf(gi) * tanhf_(gg);
            cnew[ci] = cv;
            hhiout[ci] = __float2half(sigf(go) * tanhf_(cv));
        }
    }
}

// ---------------- 1x1 projection + fused next-step mask ----------------
__global__ void xgen_k(const __half* __restrict__ hhi3,
                       const float* __restrict__ Wlast,
                       const float* __restrict__ frames, const float* __restrict__ maskT,
                       __half* __restrict__ x0hi,
                       float* __restrict__ out, int t)
{
    __shared__ float s_w[FC * NH];
    int b = blockIdx.x, tid = threadIdx.x;
    for (int i = tid; i < FC * NH; i += 256) s_w[i] = Wlast[i];
    __syncthreads();
    int pos = blockIdx.y * 128 + (tid >> 1);
    int half = tid & 1;
    size_t hb = (((size_t)(b * 256 + pos)) << 7) + half * 64;
    float acc[FC];
#pragma unroll
    for (int f = 0; f < FC; f++) acc[f] = 0.f;
    for (int ch = 0; ch < 64; ch++) {
        float hv = __half2float(hhi3[hb + ch]);
#pragma unroll
        for (int f = 0; f < FC; f++) acc[f] += hv * s_w[f * NH + half * 64 + ch];
    }
#pragma unroll
    for (int f = 0; f < FC; f++)
        acc[f] += __shfl_xor_sync(0xffffffffu, acc[f], 1);

    if (half == 0) {
        size_t ob = ((size_t)(b * NSTEP + t) * 256 + pos) * 16;
#pragma unroll
        for (int f = 0; f < FC; f++) out[ob + f] = acc[f];

        int tn = t + 1;
        if (tn < NSTEP) {
            size_t fb = ((size_t)(b * TT + tn) * 256 + pos) * 16;
            size_t xb = ((size_t)(b * 256 + pos)) * 16;
#pragma unroll
            for (int f = 0; f < FC; f++) {
                float fr = frames[fb + f];
                float v;
                if (tn < PRE) v = fr;
                else {
                    float mm = maskT[((size_t)(b * (NSTEP - PRE) + (tn - PRE)) * 256 + pos) * 16 + f];
                    v = mm * fr + (1.f - mm) * acc[f];
                }
                x0hi[xb + f] = __float2half(v);
            }
        }
    }
}

// ---------------- initial masked input (t=0) ----------------
__global__ void mask0_k(const float* __restrict__ frames, __half* __restrict__ x0hi)
{
    int idx = blockIdx.x * 256 + threadIdx.x;
    if (idx >= BB * NPOS * FC) return;
    int c = idx & 15, pos = (idx >> 4) & 255, b = idx >> 12;
    x0hi[idx] = __float2half(frames[(((size_t)(b * TT)) * 256 + pos) * 16 + c]);
}

// ---------------- losses ----------------
__global__ void mse_k(const float* __restrict__ pred, const float* __restrict__ frames,
                      float* __restrict__ acc)
{
    __shared__ float s_red[256];
    float sum = 0.f;
    for (int idx = blockIdx.x * 256 + threadIdx.x; idx < OUT_FRAMES; idx += gridDim.x * 256) {
        int c = idx & 15, pos = (idx >> 4) & 255, r = idx >> 12;
        int t = r % NSTEP, b = r / NSTEP;
        float d = pred[idx] - frames[(((size_t)(b * TT + t + 1)) * 256 + pos) * 16 + c];
        sum += d * d;
    }
    s_red[threadIdx.x] = sum;
    __syncthreads();
    for (int s = 128; s > 0; s >>= 1) {
        if (threadIdx.x < s) s_red[threadIdx.x] += s_red[threadIdx.x + s];
        __syncthreads();
    }
    if (threadIdx.x == 0) atomicAdd(&acc[0], s_red[0]);
}

__global__ void heur_k(const float* __restrict__ pred, const float* __restrict__ frames,
                       float* __restrict__ acc)
{
    int idx = threadIdx.x;
    if (idx >= NSTEP * 16) return;
    int t = idx / 16, w = idx % 16;
    float xp = 0.f, xt = 0.f;
    for (int c = 0; c < FC; c++) {
        float vals[BB]; float mx = -1e30f;
        for (int b = 0; b < BB; b++) {
            vals[b] = pred[(((size_t)(b * NSTEP + t)) * 256 + w) * 16 + c];
            mx = fmaxf(mx, vals[b]);
        }
        float s = 0.f, sw = 0.f;
        for (int b = 0; b < BB; b++) { float e = expf(vals[b] - mx); s += e; sw += e * (float)b; }
        xp += sw / s;
        mx = -1e30f;
        for (int b = 0; b < BB; b++) {
            vals[b] = frames[(((size_t)(b * TT + t + 1)) * 256 + w) * 16 + c];
            mx = fmaxf(mx, vals[b]);
        }
        s = 0.f; sw = 0.f;
        for (int b = 0; b < BB; b++) { float e = expf(vals[b] - mx); s += e; sw += e * (float)b; }
        xt += sw / s;
    }
    xp *= (1.f / FC); xt *= (1.f / FC);
    float d = xp - xt;
    atomicAdd(&acc[1], d * d);
}

__global__ void finalize_k(const float* __restrict__ acc, float* __restrict__ out_loss)
{
    out_loss[0] = acc[0] / (float)OUT_FRAMES + acc[1] / (float)(NSTEP * 16);
}

// ---------------- host orchestration ----------------
extern "C" void kernel_launch(void* const* d_in, const int* in_sizes, int n_in,
                              void* d_out, int out_size)
{
    const float* frames = (const float*)d_in[0];
    const float* maskp  = (const float*)d_in[1];
    const float* Wlast  = (const float*)d_in[10];
    float* out = (float*)d_out;

    void* p;
    cudaGetSymbolAddress(&p, g_hhi);  __half* hhi = (__half*)p;
    cudaGetSymbolAddress(&p, g_c);    float* cbuf = (float*)p;
    cudaGetSymbolAddress(&p, g_x0hi); __half* x0hi = (__half*)p;
    cudaGetSymbolAddress(&p, g_Bp);   uint4* bp = (uint4*)p;
    cudaGetSymbolAddress(&p, g_acc);  float* accb = (float*)p;

    cudaFuncSetAttribute(gemm_lstm<true>,  cudaFuncAttributeMaxDynamicSharedMemorySize, SMEMSZ);
    cudaFuncSetAttribute(gemm_lstm<false>, cudaFuncAttributeMaxDynamicSharedMemorySize, SMEMSZ);

    zero_all<<<(LAYERS * HL + 255) / 256, 256>>>(hhi, cbuf, accb);
    prepack_all<<<(BP_TOTAL + 255) / 256, 256>>>(
        (const float*)d_in[2], (const float*)d_in[3],
        (const float*)d_in[4], (const float*)d_in[5],
        (const float*)d_in[6], (const float*)d_in[7],
        (const float*)d_in[8], (const float*)d_in[9], bp);
    mask0_k<<<(BB * NPOS * FC + 255) / 256, 256>>>(frames, x0hi);

    dim3 ggrid(8, 32);
    dim3 xgrid(BB, 2);
    for (int t = 0; t < NSTEP; t++) {
        int r = t & 1, w = 1 - r;
        __half* hhr = hhi + (size_t)r * LAYERS * HL;
        __half* hhw = hhi + (size_t)w * LAYERS * HL;
        float* cr = cbuf + (size_t)r * LAYERS * HL;
        float* cw = cbuf + (size_t)w * LAYERS * HL;

        gemm_lstm<true><<<ggrid, 256, SMEMSZ>>>(
            x0hi, hhr, bp, cr, cw, hhw);
        for (int l = 1; l < LAYERS; l++) {
            gemm_lstm<false><<<ggrid, 256, SMEMSZ>>>(
                hhw + (size_t)(l - 1) * HL,
                hhr + (size_t)l * HL,
                bp + BP_L0_U4 + (size_t)(l - 1) * BP_LN_U4,
                cr + (size_t)l * HL, cw + (size_t)l * HL,
                hhw + (size_t)l * HL);
        }
        xgen_k<<<xgrid, 256>>>(hhw + (size_t)3 * HL, Wlast,
                               frames, maskp, x0hi, out, t);
    }

    mse_k<<<1024, 256>>>(out, frames, accb);
    heur_k<<<1, NSTEP * 16>>>(out, frames, accb);
    finalize_k<<<1, 1>>>(accb, out + (out_size - 1));
}

// round 17
// speedup vs baseline: 1.1356x; 1.1133x over previous
#include <cuda_runtime.h>
#include <cuda_fp16.h>
#include <math.h>
#include <stdint.h>

#define LAYERS 4
#define NH     128
#define FC     16
#define BB     16
#define TT     20
#define PRE    10
#define NPOS   256
#define NSTEP  19
#define OUT_FRAMES (BB*NSTEP*NPOS*FC)
#define HL     (BB*NPOS*NH)
#define XSZ    (BB*NPOS*FC)

#define NCH_L0   57
#define NCH_LN   100
#define BP_L0_U4 (4*NCH_L0*1024)
#define BP_LN_U4 (4*NCH_LN*1024)
#define BP_TOTAL (BP_L0_U4 + 3*BP_LN_U4)
#define TERMSZ   34560               // 240 rows * 144B max stride
#define SMEMSZ   TERMSZ

// ---------------- device scratch ----------------
__device__ __half  g_hhi[2][LAYERS][HL];
__device__ float   g_c[2][LAYERS][HL];
__device__ __half  g_x0hi[NSTEP][XSZ];     // per-t layer-0 input
__device__ uint4   g_Bp[BP_TOTAL];
__device__ float   g_acc[2];

__device__ __forceinline__ float sigf(float x) {
    return __fdividef(1.f, 1.f + __expf(-x));
}
__device__ __forceinline__ float tanhf_(float x) {
    float e = __expf(-2.f * fabsf(x));
    float r = __fdividef(1.f - e, 1.f + e);
    return copysignf(r, x);
}
__device__ __forceinline__ uint32_t smem_to_u32(const void* p) {
    uint32_t a;
    asm("{ .reg .u64 t; cvta.to.shared.u64 t, %1; cvt.u32.u64 %0, t; }" : "=r"(a) : "l"(p));
    return a;
}
__device__ __forceinline__ void ldsm4(uint32_t (&r)[4], uint32_t a) {
    asm volatile("ldmatrix.sync.aligned.m8n8.x4.shared.b16 {%0,%1,%2,%3}, [%4];"
        : "=r"(r[0]), "=r"(r[1]), "=r"(r[2]), "=r"(r[3]) : "r"(a));
}
__device__ __forceinline__ void prefetchL1(const void* p) {
    asm volatile("prefetch.global.L1 [%0];" :: "l"(p));
}
__device__ __forceinline__ void mma_f32(float (&d)[4], const uint32_t (&a)[4],
                                        uint32_t b0, uint32_t b1) {
    asm volatile("mma.sync.aligned.m16n8k16.row.col.f32.f16.f16.f32 "
        "{%0,%1,%2,%3}, {%4,%5,%6,%7}, {%8,%9}, {%0,%1,%2,%3};"
        : "+f"(d[0]), "+f"(d[1]), "+f"(d[2]), "+f"(d[3])
        : "r"(a[0]), "r"(a[1]), "r"(a[2]), "r"(a[3]), "r"(b0), "r"(b1));
}

// ---------------- fused zero init ----------------
__global__ void zero_all(__half* h1, float* c, float* acc)
{
    int i = blockIdx.x * 256 + threadIdx.x;
    const int NH2 = LAYERS * HL / 2;
    if (i < NH2) ((float*)h1)[i] = 0.f;
    if (i < LAYERS * HL) c[i] = 0.f;
    if (i < 2) acc[i] = 0.f;
}

// ---------------- weight prepack (fp16 RN), all layers ----------------
__global__ void prepack_all(const float* __restrict__ Wx0, const float* __restrict__ Wh0,
                            const float* __restrict__ Wx1, const float* __restrict__ Wh1,
                            const float* __restrict__ Wx2, const float* __restrict__ Wh2,
                            const float* __restrict__ Wx3, const float* __restrict__ Wh3,
                            uint4* __restrict__ outb)
{
    int gidx = blockIdx.x * 256 + threadIdx.x;
    if (gidx >= BP_TOTAL) return;
    const float* Wx; const float* Wh; int NCH, isL0, idx;
    if (gidx < BP_L0_U4) { Wx = Wx0; Wh = Wh0; NCH = NCH_L0; isL0 = 1; idx = gidx; }
    else {
        int r = gidx - BP_L0_U4, l = r / BP_LN_U4;
        idx = r - l * BP_LN_U4; NCH = NCH_LN; isL0 = 0;
        Wx = (l == 0) ? Wx1 : (l == 1) ? Wx2 : Wx3;
        Wh = (l == 0) ? Wh1 : (l == 1) ? Wh2 : Wh3;
    }
    int lane = idx & 31;
    int kp   = (idx >> 5) & 1;
    int n8t  = (idx >> 6) & 15;
    int rest = idx >> 10;
    int kc   = rest % NCH;
    int ntile = rest / NCH;
    int nglob = ntile * 128 + n8t * 8 + (lane >> 2);
    int hc = nglob >> 2, g = nglob & 3;

    uint32_t q[4];
#pragma unroll
    for (int j = 0; j < 4; j++) {
        uint32_t rr = 0;
#pragma unroll
        for (int h = 0; h < 2; h++) {
            int klocal = (kp * 2 + (j >> 1)) * 16 + (j & 1) * 8 + (lane & 3) * 2 + h;
            float w;
            if (isL0) {
                if (kc < 7) {
                    int ks = klocal >> 4, kk = klocal & 15;
                    int tap = kc * 4 + ks;
                    w = (tap <= 24) ? Wx[((g * 128 + hc) * 16 + kk) * 25 + tap] : 0.f;
                } else {
                    int j2 = kc - 7, seg = j2 / 25, tap = j2 % 25;
                    int c = seg * 64 + klocal;
                    w = Wh[((g * 128 + hc) * 128 + c) * 25 + tap];
                }
            } else {
                int seg = kc / 25, tap = kc % 25;
                int c = (seg & 1) * 64 + klocal;
                const float* src = (seg < 2) ? Wx : Wh;
                w = src[((g * 128 + hc) * 128 + c) * 25 + tap];
            }
            rr |= (uint32_t)__half_as_ushort(__float2half(w)) << (16 * h);
        }
        q[j] = rr;
    }
    outb[gidx] = make_uint4(q[0], q[1], q[2], q[3]);
}

// ---------------- fused mma.sync GEMM + LSTM pointwise ----------------
template<bool L0>
__global__ void __launch_bounds__(256, 2) gemm_lstm(
    const __half* __restrict__ xhi,
    const __half* __restrict__ hhi,
    const uint4* __restrict__ Bp,
    const float* __restrict__ cprev, float* __restrict__ cnew,
    __half* __restrict__ hhiout)
{
    constexpr int NCH = L0 ? NCH_L0 : NCH_LN;
    extern __shared__ __align__(128) char smem[];
    const int tid = threadIdx.x, lane = tid & 31, wid = tid >> 5;
    const int wm = wid & 3, wn = wid >> 2;
    const int nt64 = blockIdx.x, mt2 = blockIdx.y;
    const int ntile128 = nt64 >> 1, n8base = (nt64 & 1) * 8;
    const int b = mt2 >> 1, pos0 = (mt2 & 1) << 7, yb0 = (mt2 & 1) << 3;
    const uint32_t sA = smem_to_u32(smem);
    const int half16 = (lane >> 4) * 16;

    uint32_t abase144[2], abase48[2];
#pragma unroll
    for (int mt = 0; mt < 2; mt++) {
        int pos = pos0 + wm * 32 + mt * 16 + (lane & 15);
        int rowb = ((pos >> 4) - yb0) * 20 + (pos & 15);
        abase144[mt] = sA + (uint32_t)rowb * 144 + half16;
        abase48[mt]  = sA + (uint32_t)rowb * 48  + half16;
    }

    float acc[2][4][4];
#pragma unroll
    for (int a = 0; a < 2; a++)
#pragma unroll
        for (int c = 0; c < 4; c++)
#pragma unroll
            for (int d = 0; d < 4; d++) acc[a][c][d] = 0.f;

    auto stage = [&](const __half* src, int CIN, int coff, int nu4, int stride) {
        __syncthreads();
        for (int r = tid; r < 240; r += 256) {
            int yy = yb0 - 2 + r / 20, xx = r % 20 - 2;
            uint4* dst = (uint4*)(smem + r * stride);
            if (yy >= 0 && yy < 16 && xx >= 0 && xx < 16) {
                const uint4* sp = (const uint4*)(src +
                    (size_t)(((b << 8) + (yy << 4) + xx)) * CIN + coff);
                for (int j = 0; j < nu4; j++) dst[j] = sp[j];
            } else {
                uint4 z = make_uint4(0, 0, 0, 0);
                for (int j = 0; j < nu4; j++) dst[j] = z;
            }
        }
        __syncthreads();
    };

    const int fragoff = (n8base + wn * 4) * 64 + lane;

    for (int kc = 0; kc < NCH; kc++) {
        int tap = 0;
        bool xseg = false;
        if (L0) {
            if (kc < 7) {
                xseg = true;
                if (kc == 0) stage(xhi, 16, 0, 2, 48);
            } else {
                int j = kc - 7, seg = j / 25; tap = j % 25;
                if (tap == 0) stage(hhi, 128, seg * 64, 8, 144);
            }
        } else {
            int seg = kc / 25; tap = kc % 25;
            if (tap == 0)
                stage((seg < 2) ? xhi : hhi, 128, (seg & 1) * 64, 8, 144);
        }

        const uint4* bc = Bp + ((size_t)(ntile128 * NCH + kc) * 1024);
        uint4 Breg[4][2];
#pragma unroll
        for (int nt = 0; nt < 4; nt++)
#pragma unroll
            for (int kp = 0; kp < 2; kp++)
                Breg[nt][kp] = bc[fragoff + nt * 64 + kp * 32];

        if (kc + 1 < NCH && tid < 64)
            prefetchL1(bc + 1024 + n8base * 64 + tid * 8);

        int tap5y = tap / 5, tap5x = tap - tap5y * 5;
        uint32_t tapoff144 = (uint32_t)(tap5y * 20 + tap5x) * 144;

#pragma unroll
        for (int ks = 0; ks < 4; ks++) {
            uint32_t Ah[2][4];
            if (L0 && xseg) {
                int tapk = kc * 4 + ks; if (tapk > 24) tapk = 24;
                int ky = tapk / 5, kx = tapk - ky * 5;
                uint32_t off = (uint32_t)(ky * 20 + kx) * 48;
#pragma unroll
                for (int mt = 0; mt < 2; mt++)
                    ldsm4(Ah[mt], abase48[mt] + off);
            } else {
                uint32_t off = tapoff144 + (uint32_t)(ks * 32);
#pragma unroll
                for (int mt = 0; mt < 2; mt++)
                    ldsm4(Ah[mt], abase144[mt] + off);
            }
#pragma unroll
            for (int mt = 0; mt < 2; mt++) {
#pragma unroll
                for (int nt = 0; nt < 4; nt++) {
                    uint4 bh4 = Breg[nt][ks >> 1];
                    uint32_t bh0 = (ks & 1) ? bh4.z : bh4.x;
                    uint32_t bh1 = (ks & 1) ? bh4.w : bh4.y;
                    mma_f32(acc[mt][nt], Ah[mt], bh0, bh1);
                }
            }
        }
    }

    const int role = lane & 1;
#pragma unroll
    for (int mt = 0; mt < 2; mt++) {
#pragma unroll
        for (int nt = 0; nt < 4; nt++) {
            float* a = acc[mt][nt];
            float s0 = role ? a[0] : a[2];
            float s1 = role ? a[1] : a[3];
            float r0 = __shfl_xor_sync(0xffffffffu, s0, 1);
            float r1 = __shfl_xor_sync(0xffffffffu, s1, 1);
            float gi, gf, gg, go;
            int mrow;
            if (role == 0) { gi = a[0]; gf = a[1]; gg = r0; go = r1; mrow = lane >> 2; }
            else           { gi = r0;  gf = r1;  gg = a[2]; go = a[3]; mrow = (lane >> 2) + 8; }
            int pos = pos0 + wm * 32 + mt * 16 + mrow;
            int hc = nt64 * 16 + wn * 8 + nt * 2 + ((lane & 3) >> 1);
            size_t ci = ((size_t)((b << 8) + pos) << 7) + hc;
            float cv = sigf(gf + 1.0f) * cprev[ci] + sigf(gi) * tanhf_(gg);
            cnew[ci] = cv;
            hhiout[ci] = __float2half(sigf(go) * tanhf_(cv));
        }
    }
}

// ---------------- 1x1 projection; writes x0[t+1] only when t+1 >= PRE ----------
__global__ void xgen_k(const __half* __restrict__ hhi3,
                       const float* __restrict__ Wlast,
                       const float* __restrict__ frames, const float* __restrict__ maskT,
                       __half* __restrict__ x0next,
                       float* __restrict__ out, int t)
{
    __shared__ float s_w[FC * NH];
    int b = blockIdx.x, tid = threadIdx.x;
    for (int i = tid; i < FC * NH; i += 256) s_w[i] = Wlast[i];
    __syncthreads();
    int pos = blockIdx.y * 128 + (tid >> 1);
    int half = tid & 1;
    size_t hb = (((size_t)(b * 256 + pos)) << 7) + half * 64;
    float acc[FC];
#pragma unroll
    for (int f = 0; f < FC; f++) acc[f] = 0.f;
    for (int ch = 0; ch < 64; ch++) {
        float hv = __half2float(hhi3[hb + ch]);
#pragma unroll
        for (int f = 0; f < FC; f++) acc[f] += hv * s_w[f * NH + half * 64 + ch];
    }
#pragma unroll
    for (int f = 0; f < FC; f++)
        acc[f] += __shfl_xor_sync(0xffffffffu, acc[f], 1);

    if (half == 0) {
        size_t ob = ((size_t)(b * NSTEP + t) * 256 + pos) * 16;
#pragma unroll
        for (int f = 0; f < FC; f++) out[ob + f] = acc[f];

        int tn = t + 1;
        if (tn < NSTEP && tn >= PRE) {
            size_t fb = ((size_t)(b * TT + tn) * 256 + pos) * 16;
            size_t xb = ((size_t)(b * 256 + pos)) * 16;
#pragma unroll
            for (int f = 0; f < FC; f++) {
                float fr = frames[fb + f];
                float mm = maskT[((size_t)(b * (NSTEP - PRE) + (tn - PRE)) * 256 + pos) * 16 + f];
                x0next[xb + f] = __float2half(mm * fr + (1.f - mm) * acc[f]);
            }
        }
    }
}

// ---------------- precompute x0 for t = 0..PRE-1 (ground truth) ----------------
__global__ void maskpre_k(const float* __restrict__ frames, __half* __restrict__ x0all)
{
    int idx = blockIdx.x * 256 + threadIdx.x;
    int t = blockIdx.y;
    if (idx >= XSZ) return;
    int c = idx & 15, pos = (idx >> 4) & 255, b = idx >> 12;
    x0all[(size_t)t * XSZ + idx] =
        __float2half(frames[(((size_t)(b * TT + t)) * 256 + pos) * 16 + c]);
}

// ---------------- losses ----------------
__global__ void mse_k(const float* __restrict__ pred, const float* __restrict__ frames,
                      float* __restrict__ acc)
{
    __shared__ float s_red[256];
    float sum = 0.f;
    for (int idx = blockIdx.x * 256 + threadIdx.x; idx < OUT_FRAMES; idx += gridDim.x * 256) {
        int c = idx & 15, pos = (idx >> 4) & 255, r = idx >> 12;
        int t = r % NSTEP, b = r / NSTEP;
        float d = pred[idx] - frames[(((size_t)(b * TT + t + 1)) * 256 + pos) * 16 + c];
        sum += d * d;
    }
    s_red[threadIdx.x] = sum;
    __syncthreads();
    for (int s = 128; s > 0; s >>= 1) {
        if (threadIdx.x < s) s_red[threadIdx.x] += s_red[threadIdx.x + s];
        __syncthreads();
    }
    if (threadIdx.x == 0) atomicAdd(&acc[0], s_red[0]);
}

__global__ void heur_k(const float* __restrict__ pred, const float* __restrict__ frames,
                       float* __restrict__ acc)
{
    int idx = threadIdx.x;
    if (idx >= NSTEP * 16) return;
    int t = idx / 16, w = idx % 16;
    float xp = 0.f, xt = 0.f;
    for (int c = 0; c < FC; c++) {
        float vals[BB]; float mx = -1e30f;
        for (int b = 0; b < BB; b++) {
            vals[b] = pred[(((size_t)(b * NSTEP + t)) * 256 + w) * 16 + c];
            mx = fmaxf(mx, vals[b]);
        }
        float s = 0.f, sw = 0.f;
        for (int b = 0; b < BB; b++) { float e = expf(vals[b] - mx); s += e; sw += e * (float)b; }
        xp += sw / s;
        mx = -1e30f;
        for (int b = 0; b < BB; b++) {
            vals[b] = frames[(((size_t)(b * TT + t + 1)) * 256 + w) * 16 + c];
            mx = fmaxf(mx, vals[b]);
        }
        s = 0.f; sw = 0.f;
        for (int b = 0; b < BB; b++) { float e = expf(vals[b] - mx); s += e; sw += e * (float)b; }
        xt += sw / s;
    }
    xp *= (1.f / FC); xt *= (1.f / FC);
    float d = xp - xt;
    atomicAdd(&acc[1], d * d);
}

__global__ void finalize_k(const float* __restrict__ acc, float* __restrict__ out_loss)
{
    out_loss[0] = acc[0] / (float)OUT_FRAMES + acc[1] / (float)(NSTEP * 16);
}

// ---------------- host orchestration ----------------
extern "C" void kernel_launch(void* const* d_in, const int* in_sizes, int n_in,
                              void* d_out, int out_size)
{
    const float* frames = (const float*)d_in[0];
    const float* maskp  = (const float*)d_in[1];
    const float* Wlast  = (const float*)d_in[10];
    float* out = (float*)d_out;

    void* p;
    cudaGetSymbolAddress(&p, g_hhi);  __half* hhi   = (__half*)p;
    cudaGetSymbolAddress(&p, g_c);    float* cbuf   = (float*)p;
    cudaGetSymbolAddress(&p, g_x0hi); __half* x0all = (__half*)p;
    cudaGetSymbolAddress(&p, g_Bp);   uint4* bp     = (uint4*)p;
    cudaGetSymbolAddress(&p, g_acc);  float* accb   = (float*)p;

    cudaFuncSetAttribute(gemm_lstm<true>,  cudaFuncAttributeMaxDynamicSharedMemorySize, SMEMSZ);
    cudaFuncSetAttribute(gemm_lstm<false>, cudaFuncAttributeMaxDynamicSharedMemorySize, SMEMSZ);

    // one-time host resources for fork/join wavefront (no device work)
    static cudaStream_t sB = 0;
    static cudaEvent_t ev[LAYERS][PRE], evFork, evJoin;
    static int mt = 0;   // 1 = multi-stream ok, -1 = fallback single stream
    if (mt == 0) {
        bool ok = (cudaStreamCreateWithFlags(&sB, cudaStreamNonBlocking) == cudaSuccess);
        if (ok) {
            ok = (cudaEventCreateWithFlags(&evFork, cudaEventDisableTiming) == cudaSuccess)
              && (cudaEventCreateWithFlags(&evJoin, cudaEventDisableTiming) == cudaSuccess);
            for (int l = 0; l < LAYERS && ok; l++)
                for (int t = 0; t < PRE && ok; t++)
                    ok = (cudaEventCreateWithFlags(&ev[l][t], cudaEventDisableTiming) == cudaSuccess);
        }
        mt = ok ? 1 : -1;
    }

    zero_all<<<(LAYERS * HL + 255) / 256, 256>>>(hhi, cbuf, accb);
    prepack_all<<<(BP_TOTAL + 255) / 256, 256>>>(
        (const float*)d_in[2], (const float*)d_in[3],
        (const float*)d_in[4], (const float*)d_in[5],
        (const float*)d_in[6], (const float*)d_in[7],
        (const float*)d_in[8], (const float*)d_in[9], bp);
    {
        dim3 mg((XSZ + 255) / 256, PRE);
        maskpre_k<<<mg, 256>>>(frames, x0all);
    }

    dim3 ggrid(8, 32);
    dim3 xgrid(BB, 2);

    if (mt > 0) {
        cudaEventRecord(evFork, 0);
        cudaStreamWaitEvent(sB, evFork, 0);
    }

    // ---- pre-phase t = 0..9: wavefront over two streams ----
    for (int t = 0; t < PRE; t++) {
        cudaStream_t S = (mt > 0 && (t & 1)) ? sB : (cudaStream_t)0;
        int r = t & 1, w = 1 - r;
        __half* hhr = hhi + (size_t)r * LAYERS * HL;
        __half* hhw = hhi + (size_t)w * LAYERS * HL;
        float* cr = cbuf + (size_t)r * LAYERS * HL;
        float* cw = cbuf + (size_t)w * LAYERS * HL;

        for (int l = 0; l < LAYERS; l++) {
            if (mt > 0 && t > 0) cudaStreamWaitEvent(S, ev[l][t - 1], 0);
            if (l == 0) {
                gemm_lstm<true><<<ggrid, 256, SMEMSZ, S>>>(
                    x0all + (size_t)t * XSZ, hhr, bp, cr, cw, hhw);
            } else {
                gemm_lstm<false><<<ggrid, 256, SMEMSZ, S>>>(
                    hhw + (size_t)(l - 1) * HL,
                    hhr + (size_t)l * HL,
                    bp + BP_L0_U4 + (size_t)(l - 1) * BP_LN_U4,
                    cr + (size_t)l * HL, cw + (size_t)l * HL,
                    hhw + (size_t)l * HL);
            }
            if (mt > 0) cudaEventRecord(ev[l][t], S);
        }
        xgen_k<<<xgrid, 256, 0, S>>>(hhw + (size_t)3 * HL, Wlast,
                                     frames, maskp,
                                     x0all + (size_t)((t + 1 < NSTEP) ? t + 1 : 0) * XSZ,
                                     out, t);
    }

    // join side stream back before generation phase
    if (mt > 0) {
        cudaEventRecord(evJoin, sB);
        cudaStreamWaitEvent(0, evJoin, 0);
    }

    // ---- generation phase t = 10..18: serial on stream 0 ----
    for (int t = PRE; t < NSTEP; t++) {
        int r = t & 1, w = 1 - r;
        __half* hhr = hhi + (size_t)r * LAYERS * HL;
        __half* hhw = hhi + (size_t)w * LAYERS * HL;
        float* cr = cbuf + (size_t)r * LAYERS * HL;
        float* cw = cbuf + (size_t)w * LAYERS * HL;

        gemm_lstm<true><<<ggrid, 256, SMEMSZ>>>(
            x0all + (size_t)t * XSZ, hhr, bp, cr, cw, hhw);
        for (int l = 1; l < LAYERS; l++) {
            gemm_lstm<false><<<ggrid, 256, SMEMSZ>>>(
                hhw + (size_t)(l - 1) * HL,
                hhr + (size_t)l * HL,
                bp + BP_L0_U4 + (size_t)(l - 1) * BP_LN_U4,
                cr + (size_t)l * HL, cw + (size_t)l * HL,
                hhw + (size_t)l * HL);
        }
        xgen_k<<<xgrid, 256>>>(hhw + (size_t)3 * HL, Wlast,
                               frames, maskp,
                               x0all + (size_t)((t + 1 < NSTEP) ? t + 1 : 0) * XSZ,
                               out, t);
    }

    mse_k<<<1024, 256>>>(out, frames, accb);
    heur_k<<<1, NSTEP * 16>>>(out, frames, accb);
    finalize_k<<<1, 1>>>(accb, out + (out_size - 1));
}